// round 5
// baseline (speedup 1.0000x reference)
#include <cuda_runtime.h>
#include <math.h>

#define B_   16
#define M_   2048
#define E_   1024
#define H_   8
#define D_   128
#define MID_ 64
#define EPSV 1e-3f

// ---------------- scratch (device globals: the sanctioned workaround) ------
__device__ float g_q[B_*H_*D_];
__device__ float g_v1[B_*H_*D_];
__device__ float g_masksum[B_];
__device__ float g_logits[B_*H_*M_];
__device__ float g_alpha[B_*H_*M_];
__device__ float g_poolpart[B_*H_*16*MID_];   // 16 row-tiles per (b,h)
__device__ float g_alpha_ch[B_*H_*D_];
__device__ float g_part[B_*H_*16*D_];         // 16 m-slices per (b,h)
__device__ float g_v2[(size_t)B_*M_*E_];      // 128 MiB normalized v2

// ---------------------------------------------------------------------------
// Kernel 1: q = GN(elu(query@Wq+bq)), v1 = GN(elu(value1@Wv1+bv1)), masksum
// grid 32 (2 matrices x 16 rows), 256 threads
// ---------------------------------------------------------------------------
__global__ void k_smallproj(const float* __restrict__ query,
                            const float* __restrict__ value1,
                            const float* __restrict__ mask,
                            const float* __restrict__ Wq, const float* __restrict__ bq,
                            const float* __restrict__ gq, const float* __restrict__ Bq,
                            const float* __restrict__ Wv1, const float* __restrict__ bv1,
                            const float* __restrict__ gv1, const float* __restrict__ Bv1)
{
    __shared__ float xs[E_];
    __shared__ float ys[E_];
    __shared__ float red[8];
    const int blk   = blockIdx.x;
    const int which = blk >> 4;       // 0 = query path, 1 = value1 path
    const int r     = blk & 15;
    const float* x    = which ? value1 : query;
    const float* W    = which ? Wv1 : Wq;
    const float* bias = which ? bv1 : bq;
    const float* gam  = which ? gv1 : gq;
    const float* bet  = which ? Bv1 : Bq;
    float* dst        = which ? g_v1 : g_q;
    const int tid = threadIdx.x;

    #pragma unroll
    for (int c = 0; c < 4; c++) xs[tid + 256*c] = x[r*E_ + tid + 256*c];
    __syncthreads();

    float a0 = bias[tid], a1 = bias[tid+256], a2 = bias[tid+512], a3 = bias[tid+768];
    #pragma unroll 4
    for (int k = 0; k < E_; k++) {
        const float xv = xs[k];
        const float* wr = W + (size_t)k*E_ + tid;
        a0 += xv*wr[0]; a1 += xv*wr[256]; a2 += xv*wr[512]; a3 += xv*wr[768];
    }
    a0 = a0 > 0.f ? a0 : expm1f(a0);
    a1 = a1 > 0.f ? a1 : expm1f(a1);
    a2 = a2 > 0.f ? a2 : expm1f(a2);
    a3 = a3 > 0.f ? a3 : expm1f(a3);
    ys[tid] = a0; ys[tid+256] = a1; ys[tid+512] = a2; ys[tid+768] = a3;
    __syncthreads();

    const int w = tid >> 5, lane = tid & 31;     // warp w handles head w
    float v[4]; float s = 0.f, sq = 0.f;
    #pragma unroll
    for (int c = 0; c < 4; c++) {
        v[c] = ys[w*128 + lane + 32*c];
        s += v[c]; sq += v[c]*v[c];
    }
    #pragma unroll
    for (int o = 16; o > 0; o >>= 1) {
        s  += __shfl_xor_sync(0xffffffffu, s,  o);
        sq += __shfl_xor_sync(0xffffffffu, sq, o);
    }
    const float mu  = s * (1.f/128.f);
    const float var = sq * (1.f/128.f) - mu*mu;
    const float rs  = rsqrtf(var + EPSV);
    #pragma unroll
    for (int c = 0; c < 4; c++) {
        const int d = lane + 32*c;
        const int e = w*128 + d;
        dst[(r*8 + w)*128 + d] = (v[c]-mu)*rs*gam[e] + bet[e];
    }

    if (which == 0) {                 // masksum[b]
        float ms = 0.f;
        #pragma unroll
        for (int i = 0; i < 8; i++) ms += mask[r*M_ + tid + 256*i];
        #pragma unroll
        for (int o = 16; o > 0; o >>= 1) ms += __shfl_xor_sync(0xffffffffu, ms, o);
        if (lane == 0) red[w] = ms;
        __syncthreads();
        if (tid == 0) {
            float t = 0.f;
            #pragma unroll
            for (int i = 0; i < 8; i++) t += red[i];
            g_masksum[r] = t;
        }
    }
}

// ---------------------------------------------------------------------------
// Shared 128x128x1024 fp32 GEMM mainloop (BK=8), 256 threads, 8x8 microtile.
// thread (tx,ty): tx=tid&15 -> cols tx*8..+7, ty=tid>>4 -> rows ty*8..+7
// As pitch 132 (transposed, conflict-free), Bs pitch 128.
// ---------------------------------------------------------------------------
__device__ __forceinline__ void gemm_mainloop(
    const float* __restrict__ A,   // tile base: rows x 1024
    const float* __restrict__ Bw,  // W + h*128 (ld = 1024)
    float acc[8][8], float* As, float* Bs, int tid, int tx, int ty)
{
    const int arow = tid >> 1;
    const int akc  = (tid & 1) * 4;
    const int brow = tid >> 5;
    const int bcol = (tid & 31) * 4;
    for (int kt = 0; kt < E_; kt += 8) {
        const float4 av = *(const float4*)(A  + (size_t)arow*E_ + kt + akc);
        const float4 bv = *(const float4*)(Bw + (size_t)(kt + brow)*E_ + bcol);
        __syncthreads();
        As[(akc+0)*132 + arow] = av.x;
        As[(akc+1)*132 + arow] = av.y;
        As[(akc+2)*132 + arow] = av.z;
        As[(akc+3)*132 + arow] = av.w;
        *(float4*)(Bs + brow*128 + bcol) = bv;
        __syncthreads();
        #pragma unroll
        for (int k = 0; k < 8; k++) {
            const float4 A0 = *(const float4*)(As + k*132 + ty*8);
            const float4 A1 = *(const float4*)(As + k*132 + ty*8 + 4);
            const float4 B0 = *(const float4*)(Bs + k*128 + tx*8);
            const float4 B1 = *(const float4*)(Bs + k*128 + tx*8 + 4);
            const float a[8] = {A0.x,A0.y,A0.z,A0.w,A1.x,A1.y,A1.z,A1.w};
            const float b[8] = {B0.x,B0.y,B0.z,B0.w,B1.x,B1.y,B1.z,B1.w};
            #pragma unroll
            for (int i = 0; i < 8; i++)
                #pragma unroll
                for (int j = 0; j < 8; j++)
                    acc[i][j] += a[i]*b[j];
        }
    }
}

// ---------------------------------------------------------------------------
// Kernel 2: K path, fully fused.
// grid (8 heads, 256 row-tiles), 256 threads, dynamic smem 100864B.
//   C = key_tile @ Wk[:,h]  -> +bk, elu, per-row GN (128 cols = one head)
//   a = q[b,h,:] * k_norm   -> smem aS
//   basic = relu(a @ Wb + bb)
//   logit[m] = basic . Wl1 + bl1   -> g_logits
//   poolpart[tile] = sum_rows basic*mask -> g_poolpart
// ---------------------------------------------------------------------------
__global__ void __launch_bounds__(256) k_kpath(
    const float* __restrict__ key, const float* __restrict__ Wk,
    const float* __restrict__ bk,  const float* __restrict__ gk,
    const float* __restrict__ Bk,  const float* __restrict__ mask,
    const float* __restrict__ Wb,  const float* __restrict__ bb,
    const float* __restrict__ Wl1, const float* __restrict__ bl1)
{
    extern __shared__ float sm[];
    float* reg1 = sm;              // 16512 floats: [As(1056)|Bs(1024)] then aS[128*129]
    float* WbS  = sm + 16512;      // 128*68 floats; later aliased by poolS[16*64]

    const int tid = threadIdx.x;
    const int tx = tid & 15, ty = tid >> 4;
    const int h = blockIdx.x;
    const int rowBase = blockIdx.y * 128;
    const int b    = rowBase >> 11;          // /2048
    const int tile = (rowBase >> 7) & 15;
    const int bh = b*8 + h;

    for (int i = tid; i < 128*64; i += 256)
        WbS[(i>>6)*68 + (i&63)] = Wb[i];

    float acc[8][8];
    #pragma unroll
    for (int i = 0; i < 8; i++)
        #pragma unroll
        for (int j = 0; j < 8; j++) acc[i][j] = 0.f;

    gemm_mainloop(key + (size_t)rowBase*E_, Wk + h*128, acc, reg1, reg1 + 1056, tid, tx, ty);

    float biasv[8], gamv[8], betv[8], qv[8];
    #pragma unroll
    for (int j = 0; j < 8; j++) {
        const int e = h*128 + tx*8 + j;
        biasv[j] = bk[e]; gamv[j] = gk[e]; betv[j] = Bk[e];
        qv[j] = g_q[bh*128 + tx*8 + j];
    }

    __syncthreads();                 // mainloop smem reads done
    float* aS = reg1;                // pitch 129
    #pragma unroll
    for (int i = 0; i < 8; i++) {
        float vrow[8]; float s = 0.f, sq = 0.f;
        #pragma unroll
        for (int j = 0; j < 8; j++) {
            float v = acc[i][j] + biasv[j];
            v = v > 0.f ? v : expm1f(v);
            vrow[j] = v; s += v; sq += v*v;
        }
        #pragma unroll
        for (int o = 1; o < 16; o <<= 1) {   // reduce over tx (16-lane groups)
            s  += __shfl_xor_sync(0xffffffffu, s,  o);
            sq += __shfl_xor_sync(0xffffffffu, sq, o);
        }
        const float mu  = s * (1.f/128.f);
        const float var = sq * (1.f/128.f) - mu*mu;
        const float rs  = rsqrtf(var + EPSV);
        const int row = ty*8 + i;
        #pragma unroll
        for (int j = 0; j < 8; j++) {
            float a = (vrow[j]-mu)*rs*gamv[j] + betv[j];
            a *= qv[j];
            aS[row*129 + tx*8 + j] = a;
        }
    }
    __syncthreads();

    // mini-GEMM: 128x64 = aS(128x128) @ Wb(128x64); thread: rows ty*8..+7, mids tx*4..+3
    float acc2[8][4];
    #pragma unroll
    for (int i = 0; i < 8; i++)
        #pragma unroll
        for (int j = 0; j < 4; j++) acc2[i][j] = 0.f;
    for (int d = 0; d < 128; d++) {
        const float4 wv = *(const float4*)(WbS + d*68 + tx*4);
        #pragma unroll
        for (int i = 0; i < 8; i++) {
            const float a = aS[(ty*8+i)*129 + d];
            acc2[i][0] += a*wv.x; acc2[i][1] += a*wv.y;
            acc2[i][2] += a*wv.z; acc2[i][3] += a*wv.w;
        }
    }

    float bbv[4], wl1v[4];
    #pragma unroll
    for (int j = 0; j < 4; j++) {
        const int mid = tx*4 + j;
        bbv[j] = bb[mid]; wl1v[j] = Wl1[mid];
    }
    const float bl1v = bl1[0];
    float maskv[8];
    #pragma unroll
    for (int i = 0; i < 8; i++)
        maskv[i] = mask[b*M_ + tile*128 + ty*8 + i];

    float pp[4] = {0.f, 0.f, 0.f, 0.f};
    #pragma unroll
    for (int i = 0; i < 8; i++) {
        float lp = 0.f;
        #pragma unroll
        for (int j = 0; j < 4; j++) {
            float bas = acc2[i][j] + bbv[j];
            bas = bas > 0.f ? bas : 0.f;
            lp += bas * wl1v[j];
            pp[j] += bas * maskv[i];
        }
        #pragma unroll
        for (int o = 1; o < 16; o <<= 1) lp += __shfl_xor_sync(0xffffffffu, lp, o);
        if (tx == 0)
            g_logits[bh*M_ + tile*128 + ty*8 + i] = lp + bl1v;
    }

    __syncthreads();                 // WbS reads done -> alias as poolS
    float* poolS = WbS;              // [16][64]
    #pragma unroll
    for (int j = 0; j < 4; j++) poolS[ty*64 + tx*4 + j] = pp[j];
    __syncthreads();
    if (tid < 64) {
        float sum = 0.f;
        #pragma unroll
        for (int t = 0; t < 16; t++) sum += poolS[t*64 + tid];
        g_poolpart[(bh*16 + tile)*64 + tid] = sum;
    }
}

// ---------------------------------------------------------------------------
// Kernel 3: V2 path: g_v2 = GN(elu(value2@Wv2+bv2)). grid (8, 256), 256 thr.
// ---------------------------------------------------------------------------
__global__ void __launch_bounds__(256) k_vpath(
    const float* __restrict__ value2, const float* __restrict__ Wv2,
    const float* __restrict__ bv2, const float* __restrict__ gv2,
    const float* __restrict__ Bv2)
{
    __shared__ __align__(16) float As[8*132];
    __shared__ __align__(16) float Bs[8*128];
    const int tid = threadIdx.x;
    const int tx = tid & 15, ty = tid >> 4;
    const int h = blockIdx.x;
    const int rowBase = blockIdx.y * 128;

    float acc[8][8];
    #pragma unroll
    for (int i = 0; i < 8; i++)
        #pragma unroll
        for (int j = 0; j < 8; j++) acc[i][j] = 0.f;

    gemm_mainloop(value2 + (size_t)rowBase*E_, Wv2 + h*128, acc, As, Bs, tid, tx, ty);

    float biasv[8], gamv[8], betv[8];
    #pragma unroll
    for (int j = 0; j < 8; j++) {
        const int e = h*128 + tx*8 + j;
        biasv[j] = bv2[e]; gamv[j] = gv2[e]; betv[j] = Bv2[e];
    }
    #pragma unroll
    for (int i = 0; i < 8; i++) {
        float vrow[8]; float s = 0.f, sq = 0.f;
        #pragma unroll
        for (int j = 0; j < 8; j++) {
            float v = acc[i][j] + biasv[j];
            v = v > 0.f ? v : expm1f(v);
            vrow[j] = v; s += v; sq += v*v;
        }
        #pragma unroll
        for (int o = 1; o < 16; o <<= 1) {
            s  += __shfl_xor_sync(0xffffffffu, s,  o);
            sq += __shfl_xor_sync(0xffffffffu, sq, o);
        }
        const float mu  = s * (1.f/128.f);
        const float var = sq * (1.f/128.f) - mu*mu;
        const float rs  = rsqrtf(var + EPSV);
        float4 o0, o1;
        o0.x = (vrow[0]-mu)*rs*gamv[0] + betv[0];
        o0.y = (vrow[1]-mu)*rs*gamv[1] + betv[1];
        o0.z = (vrow[2]-mu)*rs*gamv[2] + betv[2];
        o0.w = (vrow[3]-mu)*rs*gamv[3] + betv[3];
        o1.x = (vrow[4]-mu)*rs*gamv[4] + betv[4];
        o1.y = (vrow[5]-mu)*rs*gamv[5] + betv[5];
        o1.z = (vrow[6]-mu)*rs*gamv[6] + betv[6];
        o1.w = (vrow[7]-mu)*rs*gamv[7] + betv[7];
        float* dst = g_v2 + (size_t)(rowBase + ty*8 + i)*E_ + h*128 + tx*8;
        *(float4*)dst = o0;
        *(float4*)(dst + 4) = o1;
    }
}

// ---------------------------------------------------------------------------
// Kernel 4: masked softmax over M per (b,h); pool reduce + alpha_ch.
// grid 128 (bh), 256 threads
// ---------------------------------------------------------------------------
__global__ void k_softmax_pool(const float* __restrict__ mask,
                               const float* __restrict__ Wl2,
                               const float* __restrict__ bl2)
{
    const int bh = blockIdx.x, b = bh >> 3;
    const int tid = threadIdx.x;
    const int w = tid >> 5, lane = tid & 31;
    __shared__ float red[8];
    __shared__ float poolv[64];

    float lg[8];
    #pragma unroll
    for (int i = 0; i < 8; i++) {
        const int m = tid + i*256;
        const float mk = mask[b*M_ + m];
        const float L = g_logits[bh*M_ + m];
        lg[i] = (mk == 0.f) ? -1e9f : L;
    }
    float mx = lg[0];
    #pragma unroll
    for (int i = 1; i < 8; i++) mx = fmaxf(mx, lg[i]);
    #pragma unroll
    for (int o = 16; o > 0; o >>= 1) mx = fmaxf(mx, __shfl_xor_sync(0xffffffffu, mx, o));
    if (lane == 0) red[w] = mx;
    __syncthreads();
    float bm = red[0];
    #pragma unroll
    for (int i = 1; i < 8; i++) bm = fmaxf(bm, red[i]);

    float sum = 0.f;
    #pragma unroll
    for (int i = 0; i < 8; i++) { lg[i] = __expf(lg[i] - bm); sum += lg[i]; }
    #pragma unroll
    for (int o = 16; o > 0; o >>= 1) sum += __shfl_xor_sync(0xffffffffu, sum, o);
    __syncthreads();
    if (lane == 0) red[w] = sum;
    __syncthreads();
    float ts = 0.f;
    #pragma unroll
    for (int i = 0; i < 8; i++) ts += red[i];
    const float inv = 1.f / ts;
    #pragma unroll
    for (int i = 0; i < 8; i++)
        g_alpha[bh*M_ + tid + i*256] = lg[i] * inv;

    if (tid < 64) {
        float s = 0.f;
        #pragma unroll
        for (int t = 0; t < 16; t++) s += g_poolpart[(bh*16 + t)*64 + tid];
        poolv[tid] = s / g_masksum[b];
    }
    __syncthreads();
    if (tid < 128) {
        float a = bl2[tid];
        #pragma unroll
        for (int mid = 0; mid < 64; mid++) a += poolv[mid] * Wl2[mid*128 + tid];
        g_alpha_ch[bh*128 + tid] = 1.f / (1.f + __expf(-a));
    }
}

// ---------------------------------------------------------------------------
// Kernel 5: v2_agg partials: grid 2048 (bh*16+slice), 128 threads (d)
// ---------------------------------------------------------------------------
__global__ void k_v2agg()
{
    const int blk = blockIdx.x;
    const int bh = blk >> 4, slice = blk & 15;
    const int b = bh >> 3, h = bh & 7;
    const int tid = threadIdx.x;
    __shared__ float al[128];
    al[tid] = g_alpha[bh*M_ + slice*128 + tid];
    __syncthreads();
    const float* base = g_v2 + (size_t)(b*M_ + slice*128)*E_ + h*128 + tid;
    float acc = 0.f;
    #pragma unroll 8
    for (int mm = 0; mm < 128; mm++)
        acc += al[mm] * base[(size_t)mm*E_];
    g_part[blk*128 + tid] = acc;
}

// ---------------------------------------------------------------------------
// Kernel 6: out = v1 * v2_agg * alpha_ch. grid 64, 256 threads
// ---------------------------------------------------------------------------
__global__ void k_final(float* __restrict__ out)
{
    const int i = blockIdx.x*256 + threadIdx.x;   // 0..16383, = bh*128+d = b*1024+e
    const int bh = i >> 7, d = i & 127;
    float s = 0.f;
    #pragma unroll
    for (int t = 0; t < 16; t++) s += g_part[(bh*16 + t)*128 + d];
    out[i] = g_v1[i] * s * g_alpha_ch[i];
}

// ---------------------------------------------------------------------------
extern "C" void kernel_launch(void* const* d_in, const int* in_sizes, int n_in,
                              void* d_out, int out_size)
{
    const float* query  = (const float*)d_in[0];
    const float* key    = (const float*)d_in[1];
    const float* mask   = (const float*)d_in[2];
    const float* value1 = (const float*)d_in[3];
    const float* value2 = (const float*)d_in[4];
    const float* Wq  = (const float*)d_in[5];
    const float* bq  = (const float*)d_in[6];
    const float* gq  = (const float*)d_in[7];
    const float* Bq  = (const float*)d_in[8];
    const float* Wk  = (const float*)d_in[9];
    const float* bk  = (const float*)d_in[10];
    const float* gk  = (const float*)d_in[11];
    const float* Bk  = (const float*)d_in[12];
    const float* Wv1 = (const float*)d_in[13];
    const float* bv1 = (const float*)d_in[14];
    const float* gv1 = (const float*)d_in[15];
    const float* Bv1 = (const float*)d_in[16];
    const float* Wv2 = (const float*)d_in[17];
    const float* bv2 = (const float*)d_in[18];
    const float* gv2 = (const float*)d_in[19];
    const float* Bv2 = (const float*)d_in[20];
    const float* Wb  = (const float*)d_in[21];
    const float* bb  = (const float*)d_in[22];
    const float* Wl1 = (const float*)d_in[23];
    const float* bl1 = (const float*)d_in[24];
    const float* Wl2 = (const float*)d_in[25];
    const float* bl2 = (const float*)d_in[26];
    float* out = (float*)d_out;

    const int SMEM_K2 = (16512 + 128*68) * 4;   // 100864 B
    cudaFuncSetAttribute(k_kpath, cudaFuncAttributeMaxDynamicSharedMemorySize, SMEM_K2);

    k_smallproj<<<32, 256>>>(query, value1, mask,
                             Wq, bq, gq, Bq, Wv1, bv1, gv1, Bv1);

    dim3 gbig(8, 256);   // (head, row-tile)
    k_kpath<<<gbig, 256, SMEM_K2>>>(key, Wk, bk, gk, Bk, mask, Wb, bb, Wl1, bl1);
    k_vpath<<<gbig, 256>>>(value2, Wv2, bv2, gv2, Bv2);
    k_softmax_pool<<<128, 256>>>(mask, Wl2, bl2);
    k_v2agg<<<2048, 128>>>();
    k_final<<<64, 256>>>(out);

    (void)in_sizes; (void)n_in; (void)out_size;
}

// round 9
// speedup vs baseline: 1.5411x; 1.5411x over previous
#include <cuda_runtime.h>
#include <cuda_bf16.h>
#include <math.h>
#include <stdint.h>

#define B_   16
#define M_   2048
#define E_   1024
#define H_   8
#define D_   128
#define MID_ 64
#define EPSV 1e-3f

// ---------------- scratch (device globals) ---------------------------------
__device__ float g_q[B_*H_*D_];
__device__ float g_v1[B_*H_*D_];
__device__ float g_masksum[B_];
__device__ float g_logits[B_*H_*M_];
__device__ float g_alpha[B_*H_*M_];
__device__ float g_poolpart[B_*H_*16*MID_];
__device__ float g_alpha_ch[B_*H_*D_];
__device__ float g_part[B_*H_*16*D_];
__device__ float g_v2[(size_t)B_*M_*E_];      // 128 MiB normalized v2
__device__ float g_WkT[E_*E_];                // Wk^T  [n][k]
__device__ float g_Wv2T[E_*E_];               // Wv2^T [n][k]

// ---------------- helpers ---------------------------------------------------
__device__ __forceinline__ uint32_t smem_u32(const void* p) {
    uint32_t a;
    asm("{ .reg .u64 t; cvta.to.shared.u64 t, %1; cvt.u32.u64 %0, t; }"
        : "=r"(a) : "l"(p));
    return a;
}
__device__ __forceinline__ void sts32(uint32_t addr, uint32_t v) {
    asm volatile("st.shared.b32 [%0], %1;" :: "r"(addr), "r"(v) : "memory");
}
__device__ __forceinline__ uint32_t packbf(__nv_bfloat16 a, __nv_bfloat16 b) {
    return (uint32_t)__bfloat16_as_ushort(a) |
           ((uint32_t)__bfloat16_as_ushort(b) << 16);
}

#define LDSM4(r0,r1,r2,r3,a) \
    asm volatile("ldmatrix.sync.aligned.m8n8.x4.shared.b16 {%0,%1,%2,%3}, [%4];" \
        : "=r"(r0), "=r"(r1), "=r"(r2), "=r"(r3) : "r"(a))

#define MMA16816(c, a, b0, b1) \
    asm volatile("mma.sync.aligned.m16n8k16.row.col.f32.bf16.bf16.f32 " \
        "{%0,%1,%2,%3},{%4,%5,%6,%7},{%8,%9},{%0,%1,%2,%3};" \
        : "+f"((c)[0]), "+f"((c)[1]), "+f"((c)[2]), "+f"((c)[3]) \
        : "r"((a)[0]), "r"((a)[1]), "r"((a)[2]), "r"((a)[3]), "r"(b0), "r"(b1))

// staging tile layout: [128 rows][32 bf16] = 64B/row, XOR swizzle on 16B groups
__device__ __forceinline__ uint32_t sw_off(int r, int g) {
    return (uint32_t)(r*64 + ((g ^ ((r >> 1) & 3)) << 4));
}

__device__ __forceinline__ void sts_hilo(uint32_t baseHi, uint32_t baseLo,
                                         int r, int cc, float4 v)
{
    const int byte = cc*2;
    const uint32_t off = sw_off(r, byte >> 4) + (byte & 15);
    const __nv_bfloat16 h0 = __float2bfloat16(v.x);
    const __nv_bfloat16 h1 = __float2bfloat16(v.y);
    const __nv_bfloat16 h2 = __float2bfloat16(v.z);
    const __nv_bfloat16 h3 = __float2bfloat16(v.w);
    sts32(baseHi + off,     packbf(h0, h1));
    sts32(baseHi + off + 4, packbf(h2, h3));
    sts32(baseLo + off,     packbf(__float2bfloat16(v.x - __bfloat162float(h0)),
                                   __float2bfloat16(v.y - __bfloat162float(h1))));
    sts32(baseLo + off + 4, packbf(__float2bfloat16(v.z - __bfloat162float(h2)),
                                   __float2bfloat16(v.w - __bfloat162float(h3))));
}

// ---------------------------------------------------------------------------
// split-bf16 tensor-core mainloop: C[128][128] = A[128x1024] @ BT[128x1024]^T
// 256 threads, warp w: wm=w&3 (32 rows), wn=w>>2 (64 cols); BK=32, 2 stages.
// stage s at sbR + s*32768: Ahi +0, Alo +8192, Bhi +16384, Blo +24576
// ---------------------------------------------------------------------------
__device__ __forceinline__ void mma_mainloop(
    const float* __restrict__ A, const float* __restrict__ BT,
    uint32_t sbR, float c[2][8][4])
{
    const int tid = threadIdx.x;
    const int lane = tid & 31, w = tid >> 5;
    const int wm = w & 3, wn = w >> 2;
    const int qi = lane >> 3, ii = lane & 7;
    const int lrow = tid >> 1, lhalf = tid & 1;

    const float* Ap = A  + (size_t)lrow*E_ + lhalf*16;
    const float* Bp = BT + (size_t)lrow*E_ + lhalf*16;

    float4 pa[4], pb[4];
    #pragma unroll
    for (int j = 0; j < 4; j++) {
        pa[j] = *(const float4*)(Ap + j*4);
        pb[j] = *(const float4*)(Bp + j*4);
    }

    for (int ck = 0; ck < 32; ck++) {
        const uint32_t st = sbR + (ck & 1)*32768;
        #pragma unroll
        for (int j = 0; j < 4; j++) {
            const int cc = lhalf*16 + j*4;
            sts_hilo(st,         st + 8192,  lrow, cc, pa[j]);
            sts_hilo(st + 16384, st + 24576, lrow, cc, pb[j]);
        }
        __syncthreads();
        if (ck < 31) {
            #pragma unroll
            for (int j = 0; j < 4; j++) {
                pa[j] = *(const float4*)(Ap + (ck+1)*32 + j*4);
                pb[j] = *(const float4*)(Bp + (ck+1)*32 + j*4);
            }
        }
        #pragma unroll
        for (int p = 0; p < 2; p++) {
            uint32_t ah[2][4], al[2][4], bh[4][4], bl[4][4];
            #pragma unroll
            for (int mt = 0; mt < 2; mt++) {
                const int r = wm*32 + mt*16 + ii + ((qi & 1) << 3);
                const int g = 2*p + (qi >> 1);
                const uint32_t off = sw_off(r, g);
                LDSM4(ah[mt][0], ah[mt][1], ah[mt][2], ah[mt][3], st + off);
                LDSM4(al[mt][0], al[mt][1], al[mt][2], al[mt][3], st + 8192 + off);
            }
            #pragma unroll
            for (int nb = 0; nb < 4; nb++) {
                const int r = wn*64 + nb*16 + ii + ((qi >> 1) << 3);
                const int g = 2*p + (qi & 1);
                const uint32_t off = sw_off(r, g);
                LDSM4(bh[nb][0], bh[nb][1], bh[nb][2], bh[nb][3], st + 16384 + off);
                LDSM4(bl[nb][0], bl[nb][1], bl[nb][2], bl[nb][3], st + 24576 + off);
            }
            #pragma unroll
            for (int mt = 0; mt < 2; mt++)
                #pragma unroll
                for (int nt = 0; nt < 8; nt++) {
                    const uint32_t* bhf = &bh[nt >> 1][(nt & 1)*2];
                    const uint32_t* blf = &bl[nt >> 1][(nt & 1)*2];
                    MMA16816(c[mt][nt], ah[mt], bhf[0], bhf[1]);
                    MMA16816(c[mt][nt], ah[mt], blf[0], blf[1]);
                    MMA16816(c[mt][nt], al[mt], bhf[0], bhf[1]);
                }
        }
        __syncthreads();
    }
}

// write fragments to Cs[128][132]
__device__ __forceinline__ void store_C(float* Cs, const float c[2][8][4], int tid)
{
    const int lane = tid & 31, w = tid >> 5;
    const int wm = w & 3, wn = w >> 2;
    const int rq = lane >> 2, cq = (lane & 3)*2;
    #pragma unroll
    for (int mt = 0; mt < 2; mt++)
        #pragma unroll
        for (int nt = 0; nt < 8; nt++) {
            const int m = wm*32 + mt*16 + rq;
            const int n = wn*64 + nt*8 + cq;
            Cs[m*132 + n]       = c[mt][nt][0];
            Cs[m*132 + n + 1]   = c[mt][nt][1];
            Cs[(m+8)*132 + n]   = c[mt][nt][2];
            Cs[(m+8)*132 + n+1] = c[mt][nt][3];
        }
}

// ---------------------------------------------------------------------------
// Kernel 0: weight transposes. grid (32,32,2), block (32,8)
// ---------------------------------------------------------------------------
__global__ void k_transpose(const float* __restrict__ Wk,
                            const float* __restrict__ Wv2)
{
    __shared__ float t[32][33];
    const int z = blockIdx.z;
    const float* S = (z == 0) ? Wk : Wv2;
    float* Dst     = (z == 0) ? g_WkT : g_Wv2T;
    const int r0 = blockIdx.y * 32, c0 = blockIdx.x * 32;
    const int tx = threadIdx.x, ty = threadIdx.y;
    #pragma unroll
    for (int i = 0; i < 4; i++)
        t[ty + 8*i][tx] = S[(size_t)(r0 + ty + 8*i)*E_ + c0 + tx];
    __syncthreads();
    #pragma unroll
    for (int i = 0; i < 4; i++)
        Dst[(size_t)(c0 + ty + 8*i)*E_ + r0 + tx] = t[tx][ty + 8*i];
}

// ---------------------------------------------------------------------------
// Kernel 1: q/v1 small projections + masksum (unchanged)
// ---------------------------------------------------------------------------
__global__ void k_smallproj(const float* __restrict__ query,
                            const float* __restrict__ value1,
                            const float* __restrict__ mask,
                            const float* __restrict__ Wq, const float* __restrict__ bq,
                            const float* __restrict__ gq, const float* __restrict__ Bq,
                            const float* __restrict__ Wv1, const float* __restrict__ bv1,
                            const float* __restrict__ gv1, const float* __restrict__ Bv1)
{
    __shared__ float xs[E_];
    __shared__ float ys[E_];
    __shared__ float red[8];
    const int blk   = blockIdx.x;
    const int which = blk >> 4;
    const int r     = blk & 15;
    const float* x    = which ? value1 : query;
    const float* W    = which ? Wv1 : Wq;
    const float* bias = which ? bv1 : bq;
    const float* gam  = which ? gv1 : gq;
    const float* bet  = which ? Bv1 : Bq;
    float* dst        = which ? g_v1 : g_q;
    const int tid = threadIdx.x;

    #pragma unroll
    for (int c = 0; c < 4; c++) xs[tid + 256*c] = x[r*E_ + tid + 256*c];
    __syncthreads();

    float a0 = bias[tid], a1 = bias[tid+256], a2 = bias[tid+512], a3 = bias[tid+768];
    #pragma unroll 4
    for (int k = 0; k < E_; k++) {
        const float xv = xs[k];
        const float* wr = W + (size_t)k*E_ + tid;
        a0 += xv*wr[0]; a1 += xv*wr[256]; a2 += xv*wr[512]; a3 += xv*wr[768];
    }
    a0 = a0 > 0.f ? a0 : expm1f(a0);
    a1 = a1 > 0.f ? a1 : expm1f(a1);
    a2 = a2 > 0.f ? a2 : expm1f(a2);
    a3 = a3 > 0.f ? a3 : expm1f(a3);
    ys[tid] = a0; ys[tid+256] = a1; ys[tid+512] = a2; ys[tid+768] = a3;
    __syncthreads();

    const int w = tid >> 5, lane = tid & 31;
    float v[4]; float s = 0.f, sq = 0.f;
    #pragma unroll
    for (int c = 0; c < 4; c++) {
        v[c] = ys[w*128 + lane + 32*c];
        s += v[c]; sq += v[c]*v[c];
    }
    #pragma unroll
    for (int o = 16; o > 0; o >>= 1) {
        s  += __shfl_xor_sync(0xffffffffu, s,  o);
        sq += __shfl_xor_sync(0xffffffffu, sq, o);
    }
    const float mu  = s * (1.f/128.f);
    const float var = sq * (1.f/128.f) - mu*mu;
    const float rs  = rsqrtf(var + EPSV);
    #pragma unroll
    for (int c = 0; c < 4; c++) {
        const int d = lane + 32*c;
        const int e = w*128 + d;
        dst[(r*8 + w)*128 + d] = (v[c]-mu)*rs*gam[e] + bet[e];
    }

    if (which == 0) {
        float ms = 0.f;
        #pragma unroll
        for (int i = 0; i < 8; i++) ms += mask[r*M_ + tid + 256*i];
        #pragma unroll
        for (int o = 16; o > 0; o >>= 1) ms += __shfl_xor_sync(0xffffffffu, ms, o);
        if (lane == 0) red[w] = ms;
        __syncthreads();
        if (tid == 0) {
            float t = 0.f;
            #pragma unroll
            for (int i = 0; i < 8; i++) t += red[i];
            g_masksum[r] = t;
        }
    }
}

// ---------------------------------------------------------------------------
// Kernel 2: K path (tensor-core GEMM + fused epilogue)
// smem: [Cs 128*132 | aS 128*129 | WbS 128*68]  (staging aliases Cs prefix)
// ---------------------------------------------------------------------------
__global__ void __launch_bounds__(256) k_kpath(
    const float* __restrict__ key,
    const float* __restrict__ bk,  const float* __restrict__ gk,
    const float* __restrict__ Bk,  const float* __restrict__ mask,
    const float* __restrict__ Wb,  const float* __restrict__ bb,
    const float* __restrict__ Wl1, const float* __restrict__ bl1)
{
    extern __shared__ float smf[];
    float* Cs  = smf;                          // 16896 floats
    float* aS  = smf + 16896;                  // 16512 floats (pitch 129)
    float* WbS = smf + 16896 + 16512;          // 8704 floats (pitch 68)
    const uint32_t sbR = smem_u32(smf);

    const int tid = threadIdx.x;
    const int tx = tid & 15, ty = tid >> 4;
    const int h = blockIdx.x;
    const int rowBase = blockIdx.y * 128;
    const int b    = rowBase >> 11;
    const int tile = (rowBase >> 7) & 15;
    const int bh = b*8 + h;

    for (int i = tid; i < 128*64; i += 256)
        WbS[(i>>6)*68 + (i&63)] = Wb[i];
    // no sync needed yet: WbS region untouched by mainloop; first use after later syncs

    float c[2][8][4];
    #pragma unroll
    for (int mt = 0; mt < 2; mt++)
        #pragma unroll
        for (int nt = 0; nt < 8; nt++)
            #pragma unroll
            for (int q = 0; q < 4; q++) c[mt][nt][q] = 0.f;

    mma_mainloop(key + (size_t)rowBase*E_, g_WkT + (size_t)h*128*E_, sbR, c);

    store_C(Cs, c, tid);

    float biasv[8], gamv[8], betv[8], qv[8];
    #pragma unroll
    for (int j = 0; j < 8; j++) {
        const int e = h*128 + tx*8 + j;
        biasv[j] = bk[e]; gamv[j] = gk[e]; betv[j] = Bk[e];
        qv[j] = g_q[bh*128 + tx*8 + j];
    }
    __syncthreads();

    #pragma unroll
    for (int i = 0; i < 8; i++) {
        float vrow[8]; float s = 0.f, sq = 0.f;
        #pragma unroll
        for (int j = 0; j < 8; j++) {
            float v = Cs[(ty*8+i)*132 + tx*8 + j] + biasv[j];
            v = v > 0.f ? v : expm1f(v);
            vrow[j] = v; s += v; sq += v*v;
        }
        #pragma unroll
        for (int o = 1; o < 16; o <<= 1) {
            s  += __shfl_xor_sync(0xffffffffu, s,  o);
            sq += __shfl_xor_sync(0xffffffffu, sq, o);
        }
        const float mu  = s * (1.f/128.f);
        const float var = sq * (1.f/128.f) - mu*mu;
        const float rs  = rsqrtf(var + EPSV);
        const int row = ty*8 + i;
        #pragma unroll
        for (int j = 0; j < 8; j++) {
            float a = (vrow[j]-mu)*rs*gamv[j] + betv[j];
            a *= qv[j];
            aS[row*129 + tx*8 + j] = a;
        }
    }
    __syncthreads();

    // mini-GEMM: 128x64 = aS(128x128) @ WbS(128x64)
    float acc2[8][4];
    #pragma unroll
    for (int i = 0; i < 8; i++)
        #pragma unroll
        for (int j = 0; j < 4; j++) acc2[i][j] = 0.f;
    for (int d = 0; d < 128; d++) {
        const float4 wv = *(const float4*)(WbS + d*68 + tx*4);
        #pragma unroll
        for (int i = 0; i < 8; i++) {
            const float a = aS[(ty*8+i)*129 + d];
            acc2[i][0] += a*wv.x; acc2[i][1] += a*wv.y;
            acc2[i][2] += a*wv.z; acc2[i][3] += a*wv.w;
        }
    }

    float bbv[4], wl1v[4];
    #pragma unroll
    for (int j = 0; j < 4; j++) {
        const int mid = tx*4 + j;
        bbv[j] = bb[mid]; wl1v[j] = Wl1[mid];
    }
    const float bl1v = bl1[0];
    float maskv[8];
    #pragma unroll
    for (int i = 0; i < 8; i++)
        maskv[i] = mask[b*M_ + tile*128 + ty*8 + i];

    float pp[4] = {0.f, 0.f, 0.f, 0.f};
    #pragma unroll
    for (int i = 0; i < 8; i++) {
        float lp = 0.f;
        #pragma unroll
        for (int j = 0; j < 4; j++) {
            float bas = acc2[i][j] + bbv[j];
            bas = bas > 0.f ? bas : 0.f;
            lp += bas * wl1v[j];
            pp[j] += bas * maskv[i];
        }
        #pragma unroll
        for (int o = 1; o < 16; o <<= 1) lp += __shfl_xor_sync(0xffffffffu, lp, o);
        if (tx == 0)
            g_logits[bh*M_ + tile*128 + ty*8 + i] = lp + bl1v;
    }

    __syncthreads();
    float* poolS = WbS;                 // alias after use
    #pragma unroll
    for (int j = 0; j < 4; j++) poolS[ty*64 + tx*4 + j] = pp[j];
    __syncthreads();
    if (tid < 64) {
        float sum = 0.f;
        #pragma unroll
        for (int t = 0; t < 16; t++) sum += poolS[t*64 + tid];
        g_poolpart[(bh*16 + tile)*64 + tid] = sum;
    }
}

// ---------------------------------------------------------------------------
// Kernel 3: V2 path (tensor-core GEMM + GN epilogue). smem: Cs only.
// ---------------------------------------------------------------------------
__global__ void __launch_bounds__(256) k_vpath(
    const float* __restrict__ value2,
    const float* __restrict__ bv2, const float* __restrict__ gv2,
    const float* __restrict__ Bv2)
{
    extern __shared__ float smf[];
    float* Cs = smf;
    const uint32_t sbR = smem_u32(smf);

    const int tid = threadIdx.x;
    const int tx = tid & 15, ty = tid >> 4;
    const int h = blockIdx.x;
    const int rowBase = blockIdx.y * 128;

    float c[2][8][4];
    #pragma unroll
    for (int mt = 0; mt < 2; mt++)
        #pragma unroll
        for (int nt = 0; nt < 8; nt++)
            #pragma unroll
            for (int q = 0; q < 4; q++) c[mt][nt][q] = 0.f;

    mma_mainloop(value2 + (size_t)rowBase*E_, g_Wv2T + (size_t)h*128*E_, sbR, c);

    store_C(Cs, c, tid);

    float biasv[8], gamv[8], betv[8];
    #pragma unroll
    for (int j = 0; j < 8; j++) {
        const int e = h*128 + tx*8 + j;
        biasv[j] = bv2[e]; gamv[j] = gv2[e]; betv[j] = Bv2[e];
    }
    __syncthreads();

    #pragma unroll
    for (int i = 0; i < 8; i++) {
        float vrow[8]; float s = 0.f, sq = 0.f;
        #pragma unroll
        for (int j = 0; j < 8; j++) {
            float v = Cs[(ty*8+i)*132 + tx*8 + j] + biasv[j];
            v = v > 0.f ? v : expm1f(v);
            vrow[j] = v; s += v; sq += v*v;
        }
        #pragma unroll
        for (int o = 1; o < 16; o <<= 1) {
            s  += __shfl_xor_sync(0xffffffffu, s,  o);
            sq += __shfl_xor_sync(0xffffffffu, sq, o);
        }
        const float mu  = s * (1.f/128.f);
        const float var = sq * (1.f/128.f) - mu*mu;
        const float rs  = rsqrtf(var + EPSV);
        float4 o0, o1;
        o0.x = (vrow[0]-mu)*rs*gamv[0] + betv[0];
        o0.y = (vrow[1]-mu)*rs*gamv[1] + betv[1];
        o0.z = (vrow[2]-mu)*rs*gamv[2] + betv[2];
        o0.w = (vrow[3]-mu)*rs*gamv[3] + betv[3];
        o1.x = (vrow[4]-mu)*rs*gamv[4] + betv[4];
        o1.y = (vrow[5]-mu)*rs*gamv[5] + betv[5];
        o1.z = (vrow[6]-mu)*rs*gamv[6] + betv[6];
        o1.w = (vrow[7]-mu)*rs*gamv[7] + betv[7];
        float* dst = g_v2 + (size_t)(rowBase + ty*8 + i)*E_ + h*128 + tx*8;
        *(float4*)dst = o0;
        *(float4*)(dst + 4) = o1;
    }
}

// ---------------------------------------------------------------------------
// Kernel 4: masked softmax + pool reduce + alpha_ch (unchanged)
// ---------------------------------------------------------------------------
__global__ void k_softmax_pool(const float* __restrict__ mask,
                               const float* __restrict__ Wl2,
                               const float* __restrict__ bl2)
{
    const int bh = blockIdx.x, b = bh >> 3;
    const int tid = threadIdx.x;
    const int w = tid >> 5, lane = tid & 31;
    __shared__ float red[8];
    __shared__ float poolv[64];

    float lg[8];
    #pragma unroll
    for (int i = 0; i < 8; i++) {
        const int m = tid + i*256;
        const float mk = mask[b*M_ + m];
        const float L = g_logits[bh*M_ + m];
        lg[i] = (mk == 0.f) ? -1e9f : L;
    }
    float mx = lg[0];
    #pragma unroll
    for (int i = 1; i < 8; i++) mx = fmaxf(mx, lg[i]);
    #pragma unroll
    for (int o = 16; o > 0; o >>= 1) mx = fmaxf(mx, __shfl_xor_sync(0xffffffffu, mx, o));
    if (lane == 0) red[w] = mx;
    __syncthreads();
    float bm = red[0];
    #pragma unroll
    for (int i = 1; i < 8; i++) bm = fmaxf(bm, red[i]);

    float sum = 0.f;
    #pragma unroll
    for (int i = 0; i < 8; i++) { lg[i] = __expf(lg[i] - bm); sum += lg[i]; }
    #pragma unroll
    for (int o = 16; o > 0; o >>= 1) sum += __shfl_xor_sync(0xffffffffu, sum, o);
    __syncthreads();
    if (lane == 0) red[w] = sum;
    __syncthreads();
    float ts = 0.f;
    #pragma unroll
    for (int i = 0; i < 8; i++) ts += red[i];
    const float inv = 1.f / ts;
    #pragma unroll
    for (int i = 0; i < 8; i++)
        g_alpha[bh*M_ + tid + i*256] = lg[i] * inv;

    if (tid < 64) {
        float s = 0.f;
        #pragma unroll
        for (int t = 0; t < 16; t++) s += g_poolpart[(bh*16 + t)*64 + tid];
        poolv[tid] = s / g_masksum[b];
    }
    __syncthreads();
    if (tid < 128) {
        float a = bl2[tid];
        #pragma unroll
        for (int mid = 0; mid < 64; mid++) a += poolv[mid] * Wl2[mid*128 + tid];
        g_alpha_ch[bh*128 + tid] = 1.f / (1.f + __expf(-a));
    }
}

// ---------------------------------------------------------------------------
// Kernel 5: v2_agg partials (unchanged)
// ---------------------------------------------------------------------------
__global__ void k_v2agg()
{
    const int blk = blockIdx.x;
    const int bh = blk >> 4, slice = blk & 15;
    const int b = bh >> 3, h = bh & 7;
    const int tid = threadIdx.x;
    __shared__ float al[128];
    al[tid] = g_alpha[bh*M_ + slice*128 + tid];
    __syncthreads();
    const float* base = g_v2 + (size_t)(b*M_ + slice*128)*E_ + h*128 + tid;
    float acc = 0.f;
    #pragma unroll 8
    for (int mm = 0; mm < 128; mm++)
        acc += al[mm] * base[(size_t)mm*E_];
    g_part[blk*128 + tid] = acc;
}

// ---------------------------------------------------------------------------
// Kernel 6: final combine (unchanged)
// ---------------------------------------------------------------------------
__global__ void k_final(float* __restrict__ out)
{
    const int i = blockIdx.x*256 + threadIdx.x;
    const int bh = i >> 7, d = i & 127;
    float s = 0.f;
    #pragma unroll
    for (int t = 0; t < 16; t++) s += g_part[(bh*16 + t)*128 + d];
    out[i] = g_v1[i] * s * g_alpha_ch[i];
}

// ---------------------------------------------------------------------------
extern "C" void kernel_launch(void* const* d_in, const int* in_sizes, int n_in,
                              void* d_out, int out_size)
{
    const float* query  = (const float*)d_in[0];
    const float* key    = (const float*)d_in[1];
    const float* mask   = (const float*)d_in[2];
    const float* value1 = (const float*)d_in[3];
    const float* value2 = (const float*)d_in[4];
    const float* Wq  = (const float*)d_in[5];
    const float* bq  = (const float*)d_in[6];
    const float* gq  = (const float*)d_in[7];
    const float* Bq  = (const float*)d_in[8];
    const float* Wk  = (const float*)d_in[9];
    const float* bk  = (const float*)d_in[10];
    const float* gk  = (const float*)d_in[11];
    const float* Bk  = (const float*)d_in[12];
    const float* Wv1 = (const float*)d_in[13];
    const float* bv1 = (const float*)d_in[14];
    const float* gv1 = (const float*)d_in[15];
    const float* Bv1 = (const float*)d_in[16];
    const float* Wv2 = (const float*)d_in[17];
    const float* bv2 = (const float*)d_in[18];
    const float* gv2 = (const float*)d_in[19];
    const float* Bv2 = (const float*)d_in[20];
    const float* Wb  = (const float*)d_in[21];
    const float* bb  = (const float*)d_in[22];
    const float* Wl1 = (const float*)d_in[23];
    const float* bl1 = (const float*)d_in[24];
    const float* Wl2 = (const float*)d_in[25];
    const float* bl2 = (const float*)d_in[26];
    float* out = (float*)d_out;

    const int SMEM_KP = (16896 + 16512 + 8704) * 4;   // 168448 B
    const int SMEM_VP = 16896 * 4;                    // 67584 B
    cudaFuncSetAttribute(k_kpath, cudaFuncAttributeMaxDynamicSharedMemorySize, SMEM_KP);
    cudaFuncSetAttribute(k_vpath, cudaFuncAttributeMaxDynamicSharedMemorySize, SMEM_VP);

    k_transpose<<<dim3(32,32,2), dim3(32,8)>>>(Wk, Wv2);
    k_smallproj<<<32, 256>>>(query, value1, mask,
                             Wq, bq, gq, Bq, Wv1, bv1, gv1, Bv1);

    dim3 gbig(8, 256);
    k_kpath<<<gbig, 256, SMEM_KP>>>(key, bk, gk, Bk, mask, Wb, bb, Wl1, bl1);
    k_vpath<<<gbig, 256, SMEM_VP>>>(value2, bv2, gv2, Bv2);
    k_softmax_pool<<<128, 256>>>(mask, Wl2, bl2);
    k_v2agg<<<2048, 128>>>();
    k_final<<<64, 256>>>(out);

    (void)in_sizes; (void)n_in; (void)out_size;
}